// round 2
// baseline (speedup 1.0000x reference)
#include <cuda_runtime.h>
#include <math.h>

// Shapes (hardcoded per problem)
#define BB 32
#define TT 64
#define FF 128
#define DD 64
#define HH 4
#define KK 32
#define SCALE 0.17677669529663687f  // 1/sqrt(32)

// ---------------------------------------------------------------------------
// Temporal attention: one block per (b, f). Rows = T = 64.
// SMEM layout (floats):
//   xs[64][64] | wq[64][32] wk[64][32] wv[64][32] | Q[64][32] K[64][33] V[64][32]
//   S[64][65] | O[64][32] | wo[32][64]
// ---------------------------------------------------------------------------
__global__ __launch_bounds__(256, 2) void temporal_kernel(
    const float* __restrict__ x,
    const float* __restrict__ wq_g, const float* __restrict__ bq_g,
    const float* __restrict__ wk_g, const float* __restrict__ bk_g,
    const float* __restrict__ wv_g, const float* __restrict__ bv_g,
    const float* __restrict__ wo_g, const float* __restrict__ bo_g,
    float* __restrict__ out)
{
    extern __shared__ float sm[];
    float* xs  = sm;                    // 64*64   = 4096
    float* wqs = xs  + 4096;            // 64*32   = 2048
    float* wks = wqs + 2048;
    float* wvs = wks + 2048;
    float* Qs  = wvs + 2048;            // 64*32
    float* Ks  = Qs  + 2048;            // 64*33   = 2112
    float* Vs  = Ks  + 2112;            // 64*32
    float* Ss  = Vs  + 2048;            // 64*65   = 4160
    float* Os  = Ss  + 4160;            // 64*32
    float* wos = Os  + 2048;            // 32*64

    const int tid = threadIdx.x;
    const int b = blockIdx.x >> 7;     // / FF
    const int f = blockIdx.x & 127;

    // Load x slice: xs[t][d] = x[b, t, f, d]
    {
        const float4* __restrict__ src =
            (const float4*)(x + (size_t)((b * TT) * FF + f) * DD);
        // row stride in float4: FF*DD/4 = 2048
        float4* dst = (float4*)xs;
        for (int i = tid; i < TT * (DD / 4); i += 256) {
            int t = i >> 4;        // 16 float4 per row
            int c = i & 15;
            dst[t * 16 + c] = src[(size_t)t * 2048 + c];
        }
    }

    // Output-projection accumulators: out tile [T=64][D=64], 16 per thread.
    float oacc[16];
#pragma unroll
    for (int j = 0; j < 16; j++) oacc[j] = 0.f;
    const int od  = tid & 63;
    const int ot0 = tid >> 6;          // 0..3 ; t = ot0 + 4*j

    for (int h = 0; h < HH; h++) {
        __syncthreads();  // previous phase done before overwriting weights
        // Load per-head weights: w[d][h][k] -> ws[d][k]; wo[h][k][d] -> wos[k][d]
        for (int i = tid; i < 2048; i += 256) {
            int d = i >> 5, k = i & 31;
            int gi = d * (HH * KK) + h * KK + k;
            wqs[i] = wq_g[gi];
            wks[i] = wk_g[gi];
            wvs[i] = wv_g[gi];
            wos[i] = wo_g[h * 2048 + i];
        }
        __syncthreads();

        // Fused QKV projection: [64 rows] x [64 d] x [32 k]
        {
            const int pn  = tid & 31;
            const int pm0 = tid >> 5;   // 0..7 ; m = pm0 + 8*j
            float aq[8], ak[8], av[8];
#pragma unroll
            for (int j = 0; j < 8; j++) { aq[j] = 0.f; ak[j] = 0.f; av[j] = 0.f; }
            for (int d = 0; d < DD; d++) {
                float wqv = wqs[d * 32 + pn];
                float wkv = wks[d * 32 + pn];
                float wvv = wvs[d * 32 + pn];
#pragma unroll
                for (int j = 0; j < 8; j++) {
                    float xv = xs[(pm0 + 8 * j) * 64 + d];
                    aq[j] += xv * wqv;
                    ak[j] += xv * wkv;
                    av[j] += xv * wvv;
                }
            }
            float bqv = bq_g[h * KK + pn];
            float bkv = bk_g[h * KK + pn];
            float bvv = bv_g[h * KK + pn];
#pragma unroll
            for (int j = 0; j < 8; j++) {
                int m = pm0 + 8 * j;
                Qs[m * 32 + pn] = (aq[j] + bqv) * SCALE;
                Ks[m * 33 + pn] = ak[j] + bkv;
                Vs[m * 32 + pn] = av[j] + bvv;
            }
        }
        __syncthreads();

        // S = Q K^T : [64 q][64 s]
        {
            const int ss  = tid & 63;
            const int sq0 = tid >> 6;   // 0..3 ; q = sq0 + 4*j
            float sa[16];
#pragma unroll
            for (int j = 0; j < 16; j++) sa[j] = 0.f;
            for (int k = 0; k < KK; k++) {
                float kv = Ks[ss * 33 + k];
#pragma unroll
                for (int j = 0; j < 16; j++)
                    sa[j] += Qs[(sq0 + 4 * j) * 32 + k] * kv;
            }
#pragma unroll
            for (int j = 0; j < 16; j++)
                Ss[(sq0 + 4 * j) * 65 + ss] = sa[j];
        }
        __syncthreads();

        // Row softmax over s (64 rows, one thread each)
        if (tid < 64) {
            float* row = Ss + tid * 65;
            float mx = row[0];
            for (int s = 1; s < 64; s++) mx = fmaxf(mx, row[s]);
            float sum = 0.f;
            for (int s = 0; s < 64; s++) { float e = __expf(row[s] - mx); row[s] = e; sum += e; }
            float inv = 1.f / sum;
            for (int s = 0; s < 64; s++) row[s] *= inv;
        }
        __syncthreads();

        // O = P V : [64 q][32 k]
        {
            const int vk  = tid & 31;
            const int vq0 = tid >> 5;   // 0..7 ; q = vq0 + 8*j
            float oa[8];
#pragma unroll
            for (int j = 0; j < 8; j++) oa[j] = 0.f;
            for (int s = 0; s < 64; s++) {
                float vv = Vs[s * 32 + vk];
#pragma unroll
                for (int j = 0; j < 8; j++)
                    oa[j] += Ss[(vq0 + 8 * j) * 65 + s] * vv;
            }
#pragma unroll
            for (int j = 0; j < 8; j++)
                Os[(vq0 + 8 * j) * 32 + vk] = oa[j];
        }
        __syncthreads();

        // Accumulate output projection: oacc[t][d] += O[t][k] * wo[h][k][d]
        for (int k = 0; k < KK; k++) {
            float wv = wos[k * 64 + od];
#pragma unroll
            for (int j = 0; j < 16; j++)
                oacc[j] += Os[(ot0 + 4 * j) * 32 + k] * wv;
        }
    }

    // Write (initialize) out
    float bov = bo_g[od];
#pragma unroll
    for (int j = 0; j < 16; j++) {
        int t = ot0 + 4 * j;
        out[(size_t)((b * TT + t) * FF + f) * DD + od] = oacc[j] + bov;
    }
}

// ---------------------------------------------------------------------------
// Feature attention: one block per (b, t). Rows = F = 128. Adds into out.
// ---------------------------------------------------------------------------
__global__ __launch_bounds__(256, 1) void feature_kernel(
    const float* __restrict__ x,
    const float* __restrict__ wq_g, const float* __restrict__ bq_g,
    const float* __restrict__ wk_g, const float* __restrict__ bk_g,
    const float* __restrict__ wv_g, const float* __restrict__ bv_g,
    const float* __restrict__ wo_g, const float* __restrict__ bo_g,
    float* __restrict__ out)
{
    extern __shared__ float sm[];
    float* xs  = sm;                    // 128*64  = 8192
    float* wqs = xs  + 8192;            // 64*32   = 2048
    float* wks = wqs + 2048;
    float* wvs = wks + 2048;
    float* Qs  = wvs + 2048;            // 128*32  = 4096
    float* Ks  = Qs  + 4096;            // 128*33  = 4224
    float* Vs  = Ks  + 4224;            // 128*32
    float* Ss  = Vs  + 4096;            // 128*129 = 16512
    float* Os  = Ss  + 16512;           // 128*32
    float* wos = Os  + 4096;            // 32*64

    const int tid = threadIdx.x;
    const int b = blockIdx.x >> 6;     // / TT
    const int t = blockIdx.x & 63;

    // Load x slice: xs[f][d] = x[b, t, f, d]  (contiguous 8192 floats)
    {
        const float4* __restrict__ src =
            (const float4*)(x + (size_t)(b * TT + t) * FF * DD);
        float4* dst = (float4*)xs;
        for (int i = tid; i < FF * DD / 4; i += 256) dst[i] = src[i];
    }

    // Output accumulators: out tile [F=128][D=64], 32 per thread.
    float oacc[32];
#pragma unroll
    for (int j = 0; j < 32; j++) oacc[j] = 0.f;
    const int od  = tid & 63;
    const int of0 = tid >> 6;          // 0..3 ; f = of0 + 4*j

    for (int h = 0; h < HH; h++) {
        __syncthreads();
        for (int i = tid; i < 2048; i += 256) {
            int d = i >> 5, k = i & 31;
            int gi = d * (HH * KK) + h * KK + k;
            wqs[i] = wq_g[gi];
            wks[i] = wk_g[gi];
            wvs[i] = wv_g[gi];
            wos[i] = wo_g[h * 2048 + i];
        }
        __syncthreads();

        // Fused QKV projection: [128 rows] x [64 d] x [32 k]
        {
            const int pn  = tid & 31;
            const int pm0 = tid >> 5;   // 0..7 ; m = pm0 + 8*j, j<16
            float aq[16], ak[16], av[16];
#pragma unroll
            for (int j = 0; j < 16; j++) { aq[j] = 0.f; ak[j] = 0.f; av[j] = 0.f; }
            for (int d = 0; d < DD; d++) {
                float wqv = wqs[d * 32 + pn];
                float wkv = wks[d * 32 + pn];
                float wvv = wvs[d * 32 + pn];
#pragma unroll
                for (int j = 0; j < 16; j++) {
                    float xv = xs[(pm0 + 8 * j) * 64 + d];
                    aq[j] += xv * wqv;
                    ak[j] += xv * wkv;
                    av[j] += xv * wvv;
                }
            }
            float bqv = bq_g[h * KK + pn];
            float bkv = bk_g[h * KK + pn];
            float bvv = bv_g[h * KK + pn];
#pragma unroll
            for (int j = 0; j < 16; j++) {
                int m = pm0 + 8 * j;
                Qs[m * 32 + pn] = (aq[j] + bqv) * SCALE;
                Ks[m * 33 + pn] = ak[j] + bkv;
                Vs[m * 32 + pn] = av[j] + bvv;
            }
        }
        __syncthreads();

        // S = Q K^T : [128 q][128 s], chunked 4 x 16 q-rows per thread
        {
            const int ss  = tid & 127;
            const int sq0 = tid >> 7;   // 0..1 ; q = sq0 + 2*(jc*16+j)
            for (int jc = 0; jc < 4; jc++) {
                float sa[16];
#pragma unroll
                for (int j = 0; j < 16; j++) sa[j] = 0.f;
                for (int k = 0; k < KK; k++) {
                    float kv = Ks[ss * 33 + k];
#pragma unroll
                    for (int j = 0; j < 16; j++)
                        sa[j] += Qs[(sq0 + 2 * (jc * 16 + j)) * 32 + k] * kv;
                }
#pragma unroll
                for (int j = 0; j < 16; j++)
                    Ss[(sq0 + 2 * (jc * 16 + j)) * 129 + ss] = sa[j];
            }
        }
        __syncthreads();

        // Row softmax over s (128 rows)
        if (tid < 128) {
            float* row = Ss + tid * 129;
            float mx = row[0];
            for (int s = 1; s < 128; s++) mx = fmaxf(mx, row[s]);
            float sum = 0.f;
            for (int s = 0; s < 128; s++) { float e = __expf(row[s] - mx); row[s] = e; sum += e; }
            float inv = 1.f / sum;
            for (int s = 0; s < 128; s++) row[s] *= inv;
        }
        __syncthreads();

        // O = P V : [128 q][32 k]
        {
            const int vk  = tid & 31;
            const int vq0 = tid >> 5;   // 0..7 ; q = vq0 + 8*j, j<16
            float oa[16];
#pragma unroll
            for (int j = 0; j < 16; j++) oa[j] = 0.f;
            for (int s = 0; s < FF; s++) {
                float vv = Vs[s * 32 + vk];
#pragma unroll
                for (int j = 0; j < 16; j++)
                    oa[j] += Ss[(vq0 + 8 * j) * 129 + s] * vv;
            }
#pragma unroll
            for (int j = 0; j < 16; j++)
                Os[(vq0 + 8 * j) * 32 + vk] = oa[j];
        }
        __syncthreads();

        // Accumulate output projection
        for (int k = 0; k < KK; k++) {
            float wv = wos[k * 64 + od];
#pragma unroll
            for (int j = 0; j < 32; j++)
                oacc[j] += Os[(of0 + 4 * j) * 32 + k] * wv;
        }
    }

    // Add into out (temporal kernel already wrote it)
    float bov = bo_g[od];
#pragma unroll
    for (int j = 0; j < 32; j++) {
        int f = of0 + 4 * j;
        size_t idx = (size_t)((b * TT + t) * FF + f) * DD + od;
        out[idx] += oacc[j] + bov;
    }
}

extern "C" void kernel_launch(void* const* d_in, const int* in_sizes, int n_in,
                              void* d_out, int out_size)
{
    const float* x = (const float*)d_in[0];
    const float *tqw, *tqb, *tkw, *tkb, *tvw, *tvb, *tow, *tob;
    const float *fqw, *fqb, *fkw, *fkb, *fvw, *fvb, *fow, *fob;

    // Disambiguate input ordering by bias sizes:
    //   reference-signature order: to_w/to_b at idx 7/8  -> in_sizes[8] == 64
    //   setup_inputs dict order:   fq_w/fq_b at idx 7/8  -> in_sizes[8] == 128
    if (in_sizes[8] == 64) {
        tqw = (const float*)d_in[1];  tqb = (const float*)d_in[2];
        tkw = (const float*)d_in[3];  tkb = (const float*)d_in[4];
        tvw = (const float*)d_in[5];  tvb = (const float*)d_in[6];
        tow = (const float*)d_in[7];  tob = (const float*)d_in[8];
        fqw = (const float*)d_in[9];  fqb = (const float*)d_in[10];
        fkw = (const float*)d_in[11]; fkb = (const float*)d_in[12];
        fvw = (const float*)d_in[13]; fvb = (const float*)d_in[14];
        fow = (const float*)d_in[15]; fob = (const float*)d_in[16];
    } else {
        tqw = (const float*)d_in[1];  tqb = (const float*)d_in[2];
        tkw = (const float*)d_in[3];  tkb = (const float*)d_in[4];
        tvw = (const float*)d_in[5];  tvb = (const float*)d_in[6];
        fqw = (const float*)d_in[7];  fqb = (const float*)d_in[8];
        fkw = (const float*)d_in[9];  fkb = (const float*)d_in[10];
        fvw = (const float*)d_in[11]; fvb = (const float*)d_in[12];
        tow = (const float*)d_in[13]; tob = (const float*)d_in[14];
        fow = (const float*)d_in[15]; fob = (const float*)d_in[16];
    }

    const int SMEM_T = 24704 * 4;   // 98816 B
    const int SMEM_F = 49408 * 4;   // 197632 B
    cudaFuncSetAttribute(temporal_kernel,
                         cudaFuncAttributeMaxDynamicSharedMemorySize, SMEM_T);
    cudaFuncSetAttribute(feature_kernel,
                         cudaFuncAttributeMaxDynamicSharedMemorySize, SMEM_F);

    temporal_kernel<<<BB * FF, 256, SMEM_T>>>(
        x, tqw, tqb, tkw, tkb, tvw, tvb, tow, tob, (float*)d_out);
    feature_kernel<<<BB * TT, 256, SMEM_F>>>(
        x, fqw, fqb, fkw, fkb, fvw, fvb, fow, fob, (float*)d_out);
}

// round 6
// speedup vs baseline: 1.6650x; 1.6650x over previous
#include <cuda_runtime.h>
#include <math.h>
#include <stdint.h>

#define BB 32
#define TT 64
#define FF 128
#define DD 64
#define HH 4
#define KK 32
// (1/sqrt(32)) * log2(e): softmax done in log2 domain with ex2
#define QSCALE (0.17677669529663687f * 1.4426950408889634f)

__device__ __forceinline__ float ex2f(float x) {
    float y;
    asm("ex2.approx.ftz.f32 %0, %1;" : "=f"(y) : "f"(x));
    return y;
}

__device__ __forceinline__ uint32_t cvt_tf32(float v) {
    uint32_t r;
    asm("cvt.rna.tf32.f32 %0, %1;" : "=r"(r) : "f"(v));
    return r;
}

// Split fp32 into tf32 hi + tf32 lo (3xTF32 compensation).
__device__ __forceinline__ void split1(float v, uint32_t& hi, uint32_t& lo) {
    hi = cvt_tf32(v);
    lo = cvt_tf32(v - __uint_as_float(hi));
}

// m16n8k8 tf32 mma, C += A*B.
__device__ __forceinline__ void mma8(float* c, const uint32_t* a, const uint32_t* b) {
    asm volatile(
        "mma.sync.aligned.m16n8k8.row.col.f32.tf32.tf32.f32 "
        "{%0,%1,%2,%3}, {%4,%5,%6,%7}, {%8,%9}, {%0,%1,%2,%3};"
        : "+f"(c[0]), "+f"(c[1]), "+f"(c[2]), "+f"(c[3])
        : "r"(a[0]), "r"(a[1]), "r"(a[2]), "r"(a[3]), "r"(b[0]), "r"(b[1]));
}

// 3xTF32 compensated mma: C += (ahi+alo)*(bhi+blo), dropping lo*lo.
__device__ __forceinline__ void mma3(float* c,
                                     const uint32_t* ahi, const uint32_t* alo,
                                     const uint32_t* bhi, const uint32_t* blo) {
    mma8(c, alo, bhi);
    mma8(c, ahi, blo);
    mma8(c, ahi, bhi);
}

// A fragment (16x8, row-major in smem, leading dim ld), split into hi/lo.
__device__ __forceinline__ void ldA2(const float* p, int ld, int lane,
                                     uint32_t* ahi, uint32_t* alo) {
    int r = lane >> 2, c = lane & 3;
    split1(p[r * ld + c],           ahi[0], alo[0]);
    split1(p[(r + 8) * ld + c],     ahi[1], alo[1]);
    split1(p[r * ld + c + 4],       ahi[2], alo[2]);
    split1(p[(r + 8) * ld + c + 4], ahi[3], alo[3]);
}

// B fragment (8x8, stored [k][n] row-major with leading dim ld), split hi/lo.
__device__ __forceinline__ void ldB2(const float* p, int ld, int lane,
                                     uint32_t* bhi, uint32_t* blo) {
    int kk = lane & 3, nn = lane >> 2;
    split1(p[kk * ld + nn],       bhi[0], blo[0]);
    split1(p[(kk + 4) * ld + nn], bhi[1], blo[1]);
}

// ---------------------------------------------------------------------------
// Temporal attention: one block per (b, f). M = T = 64 rows. 8 warps, 2 CTA/SM.
// ---------------------------------------------------------------------------
__global__ __launch_bounds__(256, 2) void temporal_kernel(
    const float* __restrict__ x,
    const float* __restrict__ wq_g, const float* __restrict__ bq_g,
    const float* __restrict__ wk_g, const float* __restrict__ bk_g,
    const float* __restrict__ wv_g, const float* __restrict__ bv_g,
    const float* __restrict__ wo_g, const float* __restrict__ bo_g,
    float* __restrict__ out)
{
    extern __shared__ float sm[];
    float* xs = sm;            // 64 x 68
    float* Wc = xs + 4352;     // 64 x 100  (Wq|Wk|Wv as [d][96])
    float* Wo = Wc + 6400;     // 32 x 68
    float* Qs = Wo + 2176;     // 64 x 36
    float* Kt = Qs + 2304;     // 32 x 68   (K transposed: [k][s])
    float* Vs = Kt + 2176;     // 64 x 36
    float* Ss = Vs + 2304;     // 64 x 68
    float* Os = Ss + 4352;     // 64 x 36

    const int tid  = threadIdx.x;
    const int lane = tid & 31;
    const int w    = tid >> 5;
    const int b    = blockIdx.x >> 7;
    const int f    = blockIdx.x & 127;

    const int mt   = w >> 1;       // m-tile 0..3 (16 rows each)
    const int half = w & 1;        // n-split
    const int row0 = mt * 16;
    const int r    = lane >> 2;
    const int qd   = lane & 3;

    // Load x slice: xs[t][d] = x[b, t, f, d]
    {
        const float4* src = (const float4*)(x + ((size_t)(b * TT) * FF + f) * DD);
        for (int i = tid; i < TT * 16; i += 256) {
            int t = i >> 4, c = i & 15;
            *(float4*)(xs + t * 68 + c * 4) = src[(size_t)t * 2048 + c];
        }
    }

    float oacc[4][4];
#pragma unroll
    for (int j = 0; j < 4; j++)
#pragma unroll
        for (int i = 0; i < 4; i++) oacc[j][i] = 0.f;

    for (int h = 0; h < HH; h++) {
        __syncthreads();
        // Stage per-head weights
        for (int i = tid; i < 64 * 96; i += 256) {
            int d = i / 96, n = i % 96;
            const float* src = (n < 32) ? wq_g : (n < 64) ? wk_g : wv_g;
            Wc[d * 100 + n] = src[d * 128 + h * 32 + (n & 31)];
        }
        for (int i = tid; i < 2048; i += 256)
            Wo[(i >> 6) * 68 + (i & 63)] = wo_g[h * 2048 + i];
        __syncthreads();

        // --- GEMM1: QKV = xs[64x64] * Wc[64x96]. warp: m-tile mt, 6 n-tiles ---
        {
            float c6[6][4];
#pragma unroll
            for (int j = 0; j < 6; j++)
#pragma unroll
                for (int i = 0; i < 4; i++) c6[j][i] = 0.f;
#pragma unroll
            for (int k0 = 0; k0 < 8; k0++) {
                uint32_t ah[4], al[4];
                ldA2(xs + row0 * 68 + k0 * 8, 68, lane, ah, al);
#pragma unroll
                for (int j = 0; j < 6; j++) {
                    int n0 = (half * 6 + j) * 8;
                    uint32_t bh[2], bl[2];
                    ldB2(Wc + k0 * 8 * 100 + n0, 100, lane, bh, bl);
                    mma3(c6[j], ah, al, bh, bl);
                }
            }
#pragma unroll
            for (int j = 0; j < 6; j++) {
                int n0 = (half * 6 + j) * 8;
                int cc = n0 + qd * 2;
                int rr = row0 + r;
                if (n0 < 32) {
                    float b0 = bq_g[h * 32 + cc], b1 = bq_g[h * 32 + cc + 1];
                    Qs[rr * 36 + cc]           = (c6[j][0] + b0) * QSCALE;
                    Qs[rr * 36 + cc + 1]       = (c6[j][1] + b1) * QSCALE;
                    Qs[(rr + 8) * 36 + cc]     = (c6[j][2] + b0) * QSCALE;
                    Qs[(rr + 8) * 36 + cc + 1] = (c6[j][3] + b1) * QSCALE;
                } else if (n0 < 64) {
                    int k = cc - 32;
                    float b0 = bk_g[h * 32 + k], b1 = bk_g[h * 32 + k + 1];
                    Kt[k * 68 + rr]           = c6[j][0] + b0;
                    Kt[(k + 1) * 68 + rr]     = c6[j][1] + b1;
                    Kt[k * 68 + rr + 8]       = c6[j][2] + b0;
                    Kt[(k + 1) * 68 + rr + 8] = c6[j][3] + b1;
                } else {
                    int vk = cc - 64;
                    float b0 = bv_g[h * 32 + vk], b1 = bv_g[h * 32 + vk + 1];
                    Vs[rr * 36 + vk]           = c6[j][0] + b0;
                    Vs[rr * 36 + vk + 1]       = c6[j][1] + b1;
                    Vs[(rr + 8) * 36 + vk]     = c6[j][2] + b0;
                    Vs[(rr + 8) * 36 + vk + 1] = c6[j][3] + b1;
                }
            }
        }
        __syncthreads();

        // --- S = Q * Kt : [64x64], K=32. warp: mt, 4 n-tiles ---
        {
            float cS[4][4];
#pragma unroll
            for (int j = 0; j < 4; j++)
#pragma unroll
                for (int i = 0; i < 4; i++) cS[j][i] = 0.f;
#pragma unroll
            for (int k0 = 0; k0 < 4; k0++) {
                uint32_t ah[4], al[4];
                ldA2(Qs + row0 * 36 + k0 * 8, 36, lane, ah, al);
#pragma unroll
                for (int j = 0; j < 4; j++) {
                    int n0 = (half * 4 + j) * 8;
                    uint32_t bh[2], bl[2];
                    ldB2(Kt + k0 * 8 * 68 + n0, 68, lane, bh, bl);
                    mma3(cS[j], ah, al, bh, bl);
                }
            }
#pragma unroll
            for (int j = 0; j < 4; j++) {
                int n0 = (half * 4 + j) * 8;
                int cc = n0 + qd * 2;
                int rr = row0 + r;
                Ss[rr * 68 + cc]           = cS[j][0];
                Ss[rr * 68 + cc + 1]       = cS[j][1];
                Ss[(rr + 8) * 68 + cc]     = cS[j][2];
                Ss[(rr + 8) * 68 + cc + 1] = cS[j][3];
            }
        }
        __syncthreads();

        // --- softmax over s (log2 domain), 4 threads/row, 16 elems each ---
        {
            int rowi = tid >> 2, q = tid & 3;
            float* p = Ss + rowi * 68 + q * 16;
            float v[16];
#pragma unroll
            for (int i = 0; i < 4; i++) ((float4*)v)[i] = ((float4*)p)[i];
            float mx = v[0];
#pragma unroll
            for (int i = 1; i < 16; i++) mx = fmaxf(mx, v[i]);
            mx = fmaxf(mx, __shfl_xor_sync(0xffffffff, mx, 1));
            mx = fmaxf(mx, __shfl_xor_sync(0xffffffff, mx, 2));
            float sum = 0.f;
#pragma unroll
            for (int i = 0; i < 16; i++) { v[i] = ex2f(v[i] - mx); sum += v[i]; }
            sum += __shfl_xor_sync(0xffffffff, sum, 1);
            sum += __shfl_xor_sync(0xffffffff, sum, 2);
            float inv = __fdividef(1.f, sum);
#pragma unroll
            for (int i = 0; i < 16; i++) v[i] *= inv;
#pragma unroll
            for (int i = 0; i < 4; i++) ((float4*)p)[i] = ((float4*)v)[i];
        }
        __syncthreads();

        // --- O = P * V : [64x32], K=64. warp: mt, 2 n-tiles ---
        {
            float cP[2][4];
#pragma unroll
            for (int j = 0; j < 2; j++)
#pragma unroll
                for (int i = 0; i < 4; i++) cP[j][i] = 0.f;
#pragma unroll
            for (int k0 = 0; k0 < 8; k0++) {
                uint32_t ah[4], al[4];
                ldA2(Ss + row0 * 68 + k0 * 8, 68, lane, ah, al);
#pragma unroll
                for (int j = 0; j < 2; j++) {
                    int n0 = (half * 2 + j) * 8;
                    uint32_t bh[2], bl[2];
                    ldB2(Vs + k0 * 8 * 36 + n0, 36, lane, bh, bl);
                    mma3(cP[j], ah, al, bh, bl);
                }
            }
#pragma unroll
            for (int j = 0; j < 2; j++) {
                int n0 = (half * 2 + j) * 8;
                int cc = n0 + qd * 2;
                int rr = row0 + r;
                Os[rr * 36 + cc]           = cP[j][0];
                Os[rr * 36 + cc + 1]       = cP[j][1];
                Os[(rr + 8) * 36 + cc]     = cP[j][2];
                Os[(rr + 8) * 36 + cc + 1] = cP[j][3];
            }
        }
        __syncthreads();

        // --- out-proj accumulate: oacc += Os[64x32] * Wo[32x64]. warp: mt, 4 n-tiles ---
#pragma unroll
        for (int k0 = 0; k0 < 4; k0++) {
            uint32_t ah[4], al[4];
            ldA2(Os + row0 * 36 + k0 * 8, 36, lane, ah, al);
#pragma unroll
            for (int j = 0; j < 4; j++) {
                int n0 = (half * 4 + j) * 8;
                uint32_t bh[2], bl[2];
                ldB2(Wo + k0 * 8 * 68 + n0, 68, lane, bh, bl);
                mma3(oacc[j], ah, al, bh, bl);
            }
        }
    }

    // Write (initialize) out: rows t, cols d
    {
        int rr = row0 + r;
#pragma unroll
        for (int j = 0; j < 4; j++) {
            int d0 = (half * 4 + j) * 8 + qd * 2;
            float bo0 = bo_g[d0], bo1 = bo_g[d0 + 1];
            size_t base0 = ((size_t)(b * TT + rr) * FF + f) * DD;
            size_t base1 = ((size_t)(b * TT + rr + 8) * FF + f) * DD;
            out[base0 + d0]     = oacc[j][0] + bo0;
            out[base0 + d0 + 1] = oacc[j][1] + bo1;
            out[base1 + d0]     = oacc[j][2] + bo0;
            out[base1 + d0 + 1] = oacc[j][3] + bo1;
        }
    }
}

// ---------------------------------------------------------------------------
// Feature attention: one block per (b, t). M = F = 128 rows. 8 warps, 1 CTA/SM.
// Adds into out (stream-ordered after temporal_kernel).
// ---------------------------------------------------------------------------
__global__ __launch_bounds__(256, 1) void feature_kernel(
    const float* __restrict__ x,
    const float* __restrict__ wq_g, const float* __restrict__ bq_g,
    const float* __restrict__ wk_g, const float* __restrict__ bk_g,
    const float* __restrict__ wv_g, const float* __restrict__ bv_g,
    const float* __restrict__ wo_g, const float* __restrict__ bo_g,
    float* __restrict__ out)
{
    extern __shared__ float sm[];
    float* xs = sm;             // 128 x 68
    float* Wc = xs + 8704;      // 64 x 100
    float* Wo = Wc + 6400;      // 32 x 68
    float* Qs = Wo + 2176;      // 128 x 36
    float* Kt = Qs + 4608;      // 32 x 133
    float* Vs = Kt + 4256;      // 128 x 36
    float* Ss = Vs + 4608;      // 128 x 132
    float* Os = Ss + 16896;     // 128 x 36

    const int tid  = threadIdx.x;
    const int lane = tid & 31;
    const int w    = tid >> 5;      // m-tile 0..7
    const int b    = blockIdx.x >> 6;
    const int t    = blockIdx.x & 63;

    const int row0 = w * 16;
    const int r    = lane >> 2;
    const int qd   = lane & 3;

    // Load x slice: xs[f][d] (contiguous 8192 floats)
    {
        const float4* src = (const float4*)(x + (size_t)(b * TT + t) * FF * DD);
        for (int i = tid; i < FF * 16; i += 256) {
            int fi = i >> 4, c = i & 15;
            *(float4*)(xs + fi * 68 + c * 4) = src[i];
        }
    }

    float oacc[8][4];
#pragma unroll
    for (int j = 0; j < 8; j++)
#pragma unroll
        for (int i = 0; i < 4; i++) oacc[j][i] = 0.f;

    for (int h = 0; h < HH; h++) {
        __syncthreads();
        for (int i = tid; i < 64 * 96; i += 256) {
            int d = i / 96, n = i % 96;
            const float* src = (n < 32) ? wq_g : (n < 64) ? wk_g : wv_g;
            Wc[d * 100 + n] = src[d * 128 + h * 32 + (n & 31)];
        }
        for (int i = tid; i < 2048; i += 256)
            Wo[(i >> 6) * 68 + (i & 63)] = wo_g[h * 2048 + i];
        __syncthreads();

        // --- GEMM1: QKV = xs[128x64] * Wc[64x96]. warp: m-tile w, 12 n-tiles ---
        {
            float c12[12][4];
#pragma unroll
            for (int j = 0; j < 12; j++)
#pragma unroll
                for (int i = 0; i < 4; i++) c12[j][i] = 0.f;
#pragma unroll
            for (int k0 = 0; k0 < 8; k0++) {
                uint32_t ah[4], al[4];
                ldA2(xs + row0 * 68 + k0 * 8, 68, lane, ah, al);
#pragma unroll
                for (int j = 0; j < 12; j++) {
                    uint32_t bh[2], bl[2];
                    ldB2(Wc + k0 * 8 * 100 + j * 8, 100, lane, bh, bl);
                    mma3(c12[j], ah, al, bh, bl);
                }
            }
#pragma unroll
            for (int j = 0; j < 12; j++) {
                int n0 = j * 8;
                int cc = n0 + qd * 2;
                int rr = row0 + r;
                if (n0 < 32) {
                    float b0 = bq_g[h * 32 + cc], b1 = bq_g[h * 32 + cc + 1];
                    Qs[rr * 36 + cc]           = (c12[j][0] + b0) * QSCALE;
                    Qs[rr * 36 + cc + 1]       = (c12[j][1] + b1) * QSCALE;
                    Qs[(rr + 8) * 36 + cc]     = (c12[j][2] + b0) * QSCALE;
                    Qs[(rr + 8) * 36 + cc + 1] = (c12[j][3] + b1) * QSCALE;
                } else if (n0 < 64) {
                    int k = cc - 32;
                    float b0 = bk_g[h * 32 + k], b1 = bk_g[h * 32 + k + 1];
                    Kt[k * 133 + rr]           = c12[j][0] + b0;
                    Kt[(k + 1) * 133 + rr]     = c12[j][1] + b1;
                    Kt[k * 133 + rr + 8]       = c12[j][2] + b0;
                    Kt[(k + 1) * 133 + rr + 8] = c12[j][3] + b1;
                } else {
                    int vk = cc - 64;
                    float b0 = bv_g[h * 32 + vk], b1 = bv_g[h * 32 + vk + 1];
                    Vs[rr * 36 + vk]           = c12[j][0] + b0;
                    Vs[rr * 36 + vk + 1]       = c12[j][1] + b1;
                    Vs[(rr + 8) * 36 + vk]     = c12[j][2] + b0;
                    Vs[(rr + 8) * 36 + vk + 1] = c12[j][3] + b1;
                }
            }
        }
        __syncthreads();

        // --- S = Q * Kt : [128x128], K=32. warp: m-tile w, 16 n-tiles ---
        {
            float cS[16][4];
#pragma unroll
            for (int j = 0; j < 16; j++)
#pragma unroll
                for (int i = 0; i < 4; i++) cS[j][i] = 0.f;
#pragma unroll
            for (int k0 = 0; k0 < 4; k0++) {
                uint32_t ah[4], al[4];
                ldA2(Qs + row0 * 36 + k0 * 8, 36, lane, ah, al);
#pragma unroll
                for (int j = 0; j < 16; j++) {
                    uint32_t bh[2], bl[2];
                    ldB2(Kt + k0 * 8 * 133 + j * 8, 133, lane, bh, bl);
                    mma3(cS[j], ah, al, bh, bl);
                }
            }
#pragma unroll
            for (int j = 0; j < 16; j++) {
                int cc = j * 8 + qd * 2;
                int rr = row0 + r;
                Ss[rr * 132 + cc]           = cS[j][0];
                Ss[rr * 132 + cc + 1]       = cS[j][1];
                Ss[(rr + 8) * 132 + cc]     = cS[j][2];
                Ss[(rr + 8) * 132 + cc + 1] = cS[j][3];
            }
        }
        __syncthreads();

        // --- softmax, 2 threads/row, 64 elems each ---
        {
            int rowi = tid >> 1, hlf = tid & 1;
            float* p = Ss + rowi * 132 + hlf * 64;
            float v[64];
#pragma unroll
            for (int i = 0; i < 16; i++) ((float4*)v)[i] = ((float4*)p)[i];
            float mx = v[0];
#pragma unroll
            for (int i = 1; i < 64; i++) mx = fmaxf(mx, v[i]);
            mx = fmaxf(mx, __shfl_xor_sync(0xffffffff, mx, 1));
            float sum = 0.f;
#pragma unroll
            for (int i = 0; i < 64; i++) { v[i] = ex2f(v[i] - mx); sum += v[i]; }
            sum += __shfl_xor_sync(0xffffffff, sum, 1);
            float inv = __fdividef(1.f, sum);
#pragma unroll
            for (int i = 0; i < 64; i++) v[i] *= inv;
#pragma unroll
            for (int i = 0; i < 16; i++) ((float4*)p)[i] = ((float4*)v)[i];
        }
        __syncthreads();

        // --- O = P * V : [128x32], K=128. warp: m-tile w, 4 n-tiles ---
        {
            float cP[4][4];
#pragma unroll
            for (int j = 0; j < 4; j++)
#pragma unroll
                for (int i = 0; i < 4; i++) cP[j][i] = 0.f;
#pragma unroll
            for (int k0 = 0; k0 < 16; k0++) {
                uint32_t ah[4], al[4];
                ldA2(Ss + row0 * 132 + k0 * 8, 132, lane, ah, al);
#pragma unroll
                for (int j = 0; j < 4; j++) {
                    uint32_t bh[2], bl[2];
                    ldB2(Vs + k0 * 8 * 36 + j * 8, 36, lane, bh, bl);
                    mma3(cP[j], ah, al, bh, bl);
                }
            }
#pragma unroll
            for (int j = 0; j < 4; j++) {
                int cc = j * 8 + qd * 2;
                int rr = row0 + r;
                Os[rr * 36 + cc]           = cP[j][0];
                Os[rr * 36 + cc + 1]       = cP[j][1];
                Os[(rr + 8) * 36 + cc]     = cP[j][2];
                Os[(rr + 8) * 36 + cc + 1] = cP[j][3];
            }
        }
        __syncthreads();

        // --- out-proj accumulate: oacc += Os[128x32] * Wo[32x64]. 8 n-tiles ---
#pragma unroll
        for (int k0 = 0; k0 < 4; k0++) {
            uint32_t ah[4], al[4];
            ldA2(Os + row0 * 36 + k0 * 8, 36, lane, ah, al);
#pragma unroll
            for (int j = 0; j < 8; j++) {
                uint32_t bh[2], bl[2];
                ldB2(Wo + k0 * 8 * 68 + j * 8, 68, lane, bh, bl);
                mma3(oacc[j], ah, al, bh, bl);
            }
        }
    }

    // Add into out: rows f, cols d
    {
        int rr = row0 + r;
#pragma unroll
        for (int j = 0; j < 8; j++) {
            int d0 = j * 8 + qd * 2;
            float bo0 = bo_g[d0], bo1 = bo_g[d0 + 1];
            size_t base0 = ((size_t)(b * TT + t) * FF + rr) * DD;
            size_t base1 = ((size_t)(b * TT + t) * FF + rr + 8) * DD;
            out[base0 + d0]     += oacc[j][0] + bo0;
            out[base0 + d0 + 1] += oacc[j][1] + bo1;
            out[base1 + d0]     += oacc[j][2] + bo0;
            out[base1 + d0 + 1] += oacc[j][3] + bo1;
        }
    }
}

extern "C" void kernel_launch(void* const* d_in, const int* in_sizes, int n_in,
                              void* d_out, int out_size)
{
    const float* x = (const float*)d_in[0];
    const float *tqw, *tqb, *tkw, *tkb, *tvw, *tvb, *tow, *tob;
    const float *fqw, *fqb, *fkw, *fkb, *fvw, *fvb, *fow, *fob;

    if (in_sizes[8] == 64) {  // reference-signature order
        tqw = (const float*)d_in[1];  tqb = (const float*)d_in[2];
        tkw = (const float*)d_in[3];  tkb = (const float*)d_in[4];
        tvw = (const float*)d_in[5];  tvb = (const float*)d_in[6];
        tow = (const float*)d_in[7];  tob = (const float*)d_in[8];
        fqw = (const float*)d_in[9];  fqb = (const float*)d_in[10];
        fkw = (const float*)d_in[11]; fkb = (const float*)d_in[12];
        fvw = (const float*)d_in[13]; fvb = (const float*)d_in[14];
        fow = (const float*)d_in[15]; fob = (const float*)d_in[16];
    } else {                  // setup_inputs dict order
        tqw = (const float*)d_in[1];  tqb = (const float*)d_in[2];
        tkw = (const float*)d_in[3];  tkb = (const float*)d_in[4];
        tvw = (const float*)d_in[5];  tvb = (const float*)d_in[6];
        fqw = (const float*)d_in[7];  fqb = (const float*)d_in[8];
        fkw = (const float*)d_in[9];  fkb = (const float*)d_in[10];
        fvw = (const float*)d_in[11]; fvb = (const float*)d_in[12];
        tow = (const float*)d_in[13]; tob = (const float*)d_in[14];
        fow = (const float*)d_in[15]; fob = (const float*)d_in[16];
    }

    const int SMEM_T = 26368 * 4;   // 105472 B -> 2 CTA/SM
    const int SMEM_F = 52256 * 4;   // 209024 B -> 1 CTA/SM
    cudaFuncSetAttribute(temporal_kernel,
                         cudaFuncAttributeMaxDynamicSharedMemorySize, SMEM_T);
    cudaFuncSetAttribute(feature_kernel,
                         cudaFuncAttributeMaxDynamicSharedMemorySize, SMEM_F);

    temporal_kernel<<<BB * FF, 256, SMEM_T>>>(
        x, tqw, tqb, tkw, tkb, tvw, tvb, tow, tob, (float*)d_out);
    feature_kernel<<<BB * TT, 256, SMEM_F>>>(
        x, fqw, fqb, fkw, fkb, fvw, fvb, fow, fob, (float*)d_out);
}

// round 7
// speedup vs baseline: 3.8700x; 2.3244x over previous
#include <cuda_runtime.h>
#include <cuda_bf16.h>
#include <math.h>
#include <stdint.h>

#define BB 32
#define TT 64
#define FF 128
#define DD 64
#define HH 4
#define KK 32
// (1/sqrt(32)) * log2(e): softmax in log2 domain with ex2
#define QSCALE (0.17677669529663687f * 1.4426950408889634f)

__device__ __forceinline__ float ex2f(float x) {
    float y;
    asm("ex2.approx.ftz.f32 %0, %1;" : "=f"(y) : "f"(x));
    return y;
}

// Split two fp32 into packed bf16 hi-pair and lo-pair (v ~= hi + lo, err ~2^-18).
__device__ __forceinline__ void split_pk(float v0, float v1, uint32_t& hi, uint32_t& lo) {
    __nv_bfloat16 h0 = __float2bfloat16(v0);
    __nv_bfloat16 h1 = __float2bfloat16(v1);
    __nv_bfloat16 l0 = __float2bfloat16(v0 - __bfloat162float(h0));
    __nv_bfloat16 l1 = __float2bfloat16(v1 - __bfloat162float(h1));
    __nv_bfloat162 H = __halves2bfloat162(h0, h1);
    __nv_bfloat162 L = __halves2bfloat162(l0, l1);
    hi = *reinterpret_cast<uint32_t*>(&H);
    lo = *reinterpret_cast<uint32_t*>(&L);
}

// m16n8k16 bf16 mma, C += A*B (fp32 accum).
__device__ __forceinline__ void mmabf(float* c, const uint32_t* a, const uint32_t* b) {
    asm volatile(
        "mma.sync.aligned.m16n8k16.row.col.f32.bf16.bf16.f32 "
        "{%0,%1,%2,%3}, {%4,%5,%6,%7}, {%8,%9}, {%0,%1,%2,%3};"
        : "+f"(c[0]), "+f"(c[1]), "+f"(c[2]), "+f"(c[3])
        : "r"(a[0]), "r"(a[1]), "r"(a[2]), "r"(a[3]), "r"(b[0]), "r"(b[1]));
}

// 3-term compensated product: C += (Ah+Al)*(Bh+Bl) - Al*Bl
__device__ __forceinline__ void mma3(float* c, const uint32_t* ah, const uint32_t* al,
                                     const uint32_t* bh, const uint32_t* bl) {
    mmabf(c, al, bh);
    mmabf(c, ah, bl);
    mmabf(c, ah, bh);
}

// A fragment from packed-bf16 smem [row][k-pair], word width W (W % 8 == 4).
__device__ __forceinline__ void ldAw(const uint32_t* p, int W, int g, int t, uint32_t* a) {
    a[0] = p[g * W + t];
    a[1] = p[(g + 8) * W + t];
    a[2] = p[g * W + t + 4];
    a[3] = p[(g + 8) * W + t + 4];
}
// B fragment from packed-bf16 smem [n][k-pair].
__device__ __forceinline__ void ldBw(const uint32_t* p, int W, int g, int t, uint32_t* b) {
    b[0] = p[g * W + t];
    b[1] = p[g * W + t + 4];
}

// ---------------------------------------------------------------------------
// Feature attention: one block per (b, t). 128 rows, 8 warps x 16 rows.
// Q, P, O live in registers; K, V, weights in packed bf16 hi/lo smem.
// ---------------------------------------------------------------------------
__global__ __launch_bounds__(256, 2) void feature_kernel(
    const float* __restrict__ x,
    const float* __restrict__ wq_g, const float* __restrict__ bq_g,
    const float* __restrict__ wk_g, const float* __restrict__ bk_g,
    const float* __restrict__ wv_g, const float* __restrict__ bv_g,
    const float* __restrict__ wo_g, const float* __restrict__ bo_g,
    float* __restrict__ out)
{
    extern __shared__ uint32_t smw[];
    uint32_t* XH  = smw;           // 128 x 36
    uint32_t* XL  = smw + 4608;
    uint32_t* WCH = smw + 9216;    // 96 x 36 (Wq|Wk|Wv, B-layout [n][k=d])
    uint32_t* WCL = smw + 12672;
    uint32_t* WOH = smw + 16128;   // 64 x 20 (B-layout [d][k=vk])
    uint32_t* WOL = smw + 17408;
    uint32_t* KTH = smw + 18688;   // 128 x 20 (B-layout [s][k=kd])
    uint32_t* KTL = smw + 21248;
    uint32_t* VTH = smw + 23808;   // 32 x 68 (B-layout [vk][k=s])
    uint32_t* VTL = smw + 25984;   // total 28160 words = 112640 B

    const int tid  = threadIdx.x;
    const int lane = tid & 31;
    const int w    = tid >> 5;
    const int g    = lane >> 2;
    const int t    = lane & 3;
    const int b    = blockIdx.x >> 6;
    const int tt   = blockIdx.x & 63;
    const int row0 = w * 16;
    const int rrA  = row0 + g, rrB = row0 + g + 8;

    // Stage x slice (contiguous [128][64]) as bf16 hi/lo pairs
    {
        const float* xp = x + (size_t)(b * TT + tt) * (FF * DD);
        for (int i = tid; i < FF * 32; i += 256) {
            int row = i >> 5, dp = i & 31;
            float2 v = *(const float2*)(xp + row * 64 + 2 * dp);
            split_pk(v.x, v.y, XH[row * 36 + dp], XL[row * 36 + dp]);
        }
    }

    float oacc[8][4];
#pragma unroll
    for (int j = 0; j < 8; j++)
#pragma unroll
        for (int i = 0; i < 4; i++) oacc[j][i] = 0.f;

    for (int h = 0; h < HH; h++) {
        __syncthreads();   // guard smem reuse (and x staging on h=0)
        // Stage Wc [n=96][k=64]
        for (int i = tid; i < 96 * 32; i += 256) {
            int n = i % 96, dp = i / 96;
            const float* src = (n < 32) ? wq_g : (n < 64) ? wk_g : wv_g;
            int nn = n & 31;
            float v0 = src[(2 * dp) * 128 + h * 32 + nn];
            float v1 = src[(2 * dp + 1) * 128 + h * 32 + nn];
            split_pk(v0, v1, WCH[n * 36 + dp], WCL[n * 36 + dp]);
        }
        // Stage Wo [n=d 64][k=vk 32]
        for (int i = tid; i < 64 * 16; i += 256) {
            int d = i & 63, kp = i >> 6;
            float v0 = wo_g[h * 2048 + (2 * kp) * 64 + d];
            float v1 = wo_g[h * 2048 + (2 * kp + 1) * 64 + d];
            split_pk(v0, v1, WOH[d * 20 + kp], WOL[d * 20 + kp]);
        }
        __syncthreads();

        // --- GEMM1: [16 rows] x [k=64] x [n=96] ---
        float c12[12][4];
#pragma unroll
        for (int j = 0; j < 12; j++)
#pragma unroll
            for (int i = 0; i < 4; i++) c12[j][i] = 0.f;
        for (int kk = 0; kk < 4; kk++) {
            uint32_t ah[4], al[4];
            ldAw(XH + row0 * 36 + kk * 8, 36, g, t, ah);
            ldAw(XL + row0 * 36 + kk * 8, 36, g, t, al);
#pragma unroll
            for (int j = 0; j < 12; j++) {
                uint32_t bh2[2], bl2[2];
                ldBw(WCH + j * 8 * 36 + kk * 8, 36, g, t, bh2);
                ldBw(WCL + j * 8 * 36 + kk * 8, 36, g, t, bl2);
                mma3(c12[j], ah, al, bh2, bl2);
            }
        }
        // Epilogue: Q -> registers (A-frag layout), K -> smem, V -> smem transposed
        uint32_t QAh[2][4], QAl[2][4];
#pragma unroll
        for (int j = 0; j < 4; j++) {
            int cc = j * 8 + 2 * t;
            float b0 = bq_g[h * 32 + cc], b1 = bq_g[h * 32 + cc + 1];
            float v0 = (c12[j][0] + b0) * QSCALE, v1 = (c12[j][1] + b1) * QSCALE;
            float v2 = (c12[j][2] + b0) * QSCALE, v3 = (c12[j][3] + b1) * QSCALE;
            int kc = j >> 1, e = j & 1;
            split_pk(v0, v1, QAh[kc][2 * e],     QAl[kc][2 * e]);
            split_pk(v2, v3, QAh[kc][2 * e + 1], QAl[kc][2 * e + 1]);
        }
#pragma unroll
        for (int j = 4; j < 8; j++) {
            int cc = (j - 4) * 8 + 2 * t;
            float b0 = bk_g[h * 32 + cc], b1 = bk_g[h * 32 + cc + 1];
            int kp = cc >> 1;
            split_pk(c12[j][0] + b0, c12[j][1] + b1, KTH[rrA * 20 + kp], KTL[rrA * 20 + kp]);
            split_pk(c12[j][2] + b0, c12[j][3] + b1, KTH[rrB * 20 + kp], KTL[rrB * 20 + kp]);
        }
        {
            __nv_bfloat16* VH16 = reinterpret_cast<__nv_bfloat16*>(VTH);
            __nv_bfloat16* VL16 = reinterpret_cast<__nv_bfloat16*>(VTL);
#pragma unroll
            for (int j = 8; j < 12; j++) {
                int vk = (j - 8) * 8 + 2 * t;
                float b0 = bv_g[h * 32 + vk], b1 = bv_g[h * 32 + vk + 1];
                float vv[4] = {c12[j][0] + b0, c12[j][1] + b1, c12[j][2] + b0, c12[j][3] + b1};
                int   cl[4] = {vk, vk + 1, vk, vk + 1};
                int   rw[4] = {rrA, rrA, rrB, rrB};
#pragma unroll
                for (int q2 = 0; q2 < 4; q2++) {
                    __nv_bfloat16 hb = __float2bfloat16(vv[q2]);
                    float lf = vv[q2] - __bfloat162float(hb);
                    VH16[cl[q2] * 136 + rw[q2]] = hb;
                    VL16[cl[q2] * 136 + rw[q2]] = __float2bfloat16(lf);
                }
            }
        }
        __syncthreads();   // K, V visible

        // --- S = Q K^T with online softmax, fused PV. 4 chunks of 32 cols ---
        float cP[4][4];
#pragma unroll
        for (int j = 0; j < 4; j++)
#pragma unroll
            for (int i = 0; i < 4; i++) cP[j][i] = 0.f;
        float mrA = -1e30f, mrB = -1e30f, sA = 0.f, sB = 0.f;

        for (int c = 0; c < 4; c++) {
            float cS[4][4];
#pragma unroll
            for (int j = 0; j < 4; j++)
#pragma unroll
                for (int i = 0; i < 4; i++) cS[j][i] = 0.f;
#pragma unroll
            for (int kk = 0; kk < 2; kk++) {
#pragma unroll
                for (int j = 0; j < 4; j++) {
                    uint32_t bh2[2], bl2[2];
                    ldBw(KTH + (c * 4 + j) * 8 * 20 + kk * 8, 20, g, t, bh2);
                    ldBw(KTL + (c * 4 + j) * 8 * 20 + kk * 8, 20, g, t, bl2);
                    mma3(cS[j], QAh[kk], QAl[kk], bh2, bl2);
                }
            }
            float mA = cS[0][0], mB = cS[0][2];
#pragma unroll
            for (int j = 0; j < 4; j++) {
                mA = fmaxf(mA, fmaxf(cS[j][0], cS[j][1]));
                mB = fmaxf(mB, fmaxf(cS[j][2], cS[j][3]));
            }
            mA = fmaxf(mA, __shfl_xor_sync(0xffffffff, mA, 1));
            mA = fmaxf(mA, __shfl_xor_sync(0xffffffff, mA, 2));
            mB = fmaxf(mB, __shfl_xor_sync(0xffffffff, mB, 1));
            mB = fmaxf(mB, __shfl_xor_sync(0xffffffff, mB, 2));
            float nmA = fmaxf(mrA, mA), nmB = fmaxf(mrB, mB);
            float scA = ex2f(mrA - nmA), scB = ex2f(mrB - nmB);
            float chA = 0.f, chB = 0.f;
#pragma unroll
            for (int j = 0; j < 4; j++) {
                cS[j][0] = ex2f(cS[j][0] - nmA); chA += cS[j][0];
                cS[j][1] = ex2f(cS[j][1] - nmA); chA += cS[j][1];
                cS[j][2] = ex2f(cS[j][2] - nmB); chB += cS[j][2];
                cS[j][3] = ex2f(cS[j][3] - nmB); chB += cS[j][3];
            }
            sA = sA * scA + chA;
            sB = sB * scB + chB;
#pragma unroll
            for (int j = 0; j < 4; j++) {
                cP[j][0] *= scA; cP[j][1] *= scA;
                cP[j][2] *= scB; cP[j][3] *= scB;
            }
            uint32_t ph[2][4], pl[2][4];
#pragma unroll
            for (int k0e = 0; k0e < 2; k0e++) {
                int j0 = 2 * k0e;
                split_pk(cS[j0][0],     cS[j0][1],     ph[k0e][0], pl[k0e][0]);
                split_pk(cS[j0][2],     cS[j0][3],     ph[k0e][1], pl[k0e][1]);
                split_pk(cS[j0 + 1][0], cS[j0 + 1][1], ph[k0e][2], pl[k0e][2]);
                split_pk(cS[j0 + 1][2], cS[j0 + 1][3], ph[k0e][3], pl[k0e][3]);
            }
#pragma unroll
            for (int k0e = 0; k0e < 2; k0e++) {
                int kkv = 2 * c + k0e;
#pragma unroll
                for (int j = 0; j < 4; j++) {
                    uint32_t bh2[2], bl2[2];
                    ldBw(VTH + j * 8 * 68 + kkv * 8, 68, g, t, bh2);
                    ldBw(VTL + j * 8 * 68 + kkv * 8, 68, g, t, bl2);
                    mma3(cP[j], ph[k0e], pl[k0e], bh2, bl2);
                }
            }
            mrA = nmA; mrB = nmB;
        }
        sA += __shfl_xor_sync(0xffffffff, sA, 1);
        sA += __shfl_xor_sync(0xffffffff, sA, 2);
        sB += __shfl_xor_sync(0xffffffff, sB, 1);
        sB += __shfl_xor_sync(0xffffffff, sB, 2);
        float invA = __fdividef(1.f, sA), invB = __fdividef(1.f, sB);
#pragma unroll
        for (int j = 0; j < 4; j++) {
            cP[j][0] *= invA; cP[j][1] *= invA;
            cP[j][2] *= invB; cP[j][3] *= invB;
        }

        // O -> registers (A-frag layout), outproj accumulate
        uint32_t OAh[2][4], OAl[2][4];
#pragma unroll
        for (int j = 0; j < 4; j++) {
            int kc = j >> 1, e = j & 1;
            split_pk(cP[j][0], cP[j][1], OAh[kc][2 * e],     OAl[kc][2 * e]);
            split_pk(cP[j][2], cP[j][3], OAh[kc][2 * e + 1], OAl[kc][2 * e + 1]);
        }
#pragma unroll
        for (int kk = 0; kk < 2; kk++) {
#pragma unroll
            for (int j = 0; j < 8; j++) {
                uint32_t bh2[2], bl2[2];
                ldBw(WOH + j * 8 * 20 + kk * 8, 20, g, t, bh2);
                ldBw(WOL + j * 8 * 20 + kk * 8, 20, g, t, bl2);
                mma3(oacc[j], OAh[kk], OAl[kk], bh2, bl2);
            }
        }
    }

    // Add into out (temporal initialized it). rows = f, cols = d
#pragma unroll
    for (int j = 0; j < 8; j++) {
        int d0 = j * 8 + 2 * t;
        float bo0 = bo_g[d0], bo1 = bo_g[d0 + 1];
        size_t base0 = ((size_t)(b * TT + tt) * FF + rrA) * DD;
        size_t base1 = ((size_t)(b * TT + tt) * FF + rrB) * DD;
        out[base0 + d0]     += oacc[j][0] + bo0;
        out[base0 + d0 + 1] += oacc[j][1] + bo1;
        out[base1 + d0]     += oacc[j][2] + bo0;
        out[base1 + d0 + 1] += oacc[j][3] + bo1;
    }
}

// ---------------------------------------------------------------------------
// Temporal attention: one block per (b, f-pair). 2 sub-blocks x 64 rows (T).
// warps 0-3 -> f0, warps 4-7 -> f0+1. Writes (initializes) out.
// ---------------------------------------------------------------------------
__global__ __launch_bounds__(256, 2) void temporal_kernel(
    const float* __restrict__ x,
    const float* __restrict__ wq_g, const float* __restrict__ bq_g,
    const float* __restrict__ wk_g, const float* __restrict__ bk_g,
    const float* __restrict__ wv_g, const float* __restrict__ bv_g,
    const float* __restrict__ wo_g, const float* __restrict__ bo_g,
    float* __restrict__ out)
{
    extern __shared__ uint32_t smw[];
    uint32_t* XH  = smw;           // 2 x (64 x 36)
    uint32_t* XL  = smw + 4608;
    uint32_t* WCH = smw + 9216;    // 96 x 36
    uint32_t* WCL = smw + 12672;
    uint32_t* WOH = smw + 16128;   // 64 x 20
    uint32_t* WOL = smw + 17408;
    uint32_t* KTH = smw + 18688;   // 2 x (64 x 20)
    uint32_t* KTL = smw + 21248;
    uint32_t* VTH = smw + 23808;   // 2 x (32 x 36)
    uint32_t* VTL = smw + 26112;   // total 28416 words = 113664 B

    const int tid  = threadIdx.x;
    const int lane = tid & 31;
    const int w    = tid >> 5;
    const int g    = lane >> 2;
    const int t    = lane & 3;
    const int b    = blockIdx.x >> 6;
    const int f0   = (blockIdx.x & 63) * 2;
    const int sub  = w >> 2;
    const int row0 = (w & 3) * 16;
    const int rrA  = row0 + g, rrB = row0 + g + 8;
    const int f    = f0 + sub;

    uint32_t* XHs  = XH + sub * 2304;
    uint32_t* XLs  = XL + sub * 2304;
    uint32_t* KTHs = KTH + sub * 1280;
    uint32_t* KTLs = KTL + sub * 1280;
    uint32_t* VTHs = VTH + sub * 1152;
    uint32_t* VTLs = VTL + sub * 1152;

    // Stage x slices for both f's: xs[s][row=t][k=d]
    for (int i = tid; i < 2 * 64 * 32; i += 256) {
        int s = i >> 11, rem = i & 2047, row = rem >> 5, dp = rem & 31;
        const float* xp = x + ((size_t)(b * TT + row) * FF + (f0 + s)) * DD;
        float2 v = *(const float2*)(xp + 2 * dp);
        split_pk(v.x, v.y, XH[s * 2304 + row * 36 + dp], XL[s * 2304 + row * 36 + dp]);
    }

    float oacc[8][4];
#pragma unroll
    for (int j = 0; j < 8; j++)
#pragma unroll
        for (int i = 0; i < 4; i++) oacc[j][i] = 0.f;

    for (int h = 0; h < HH; h++) {
        __syncthreads();
        for (int i = tid; i < 96 * 32; i += 256) {
            int n = i % 96, dp = i / 96;
            const float* src = (n < 32) ? wq_g : (n < 64) ? wk_g : wv_g;
            int nn = n & 31;
            float v0 = src[(2 * dp) * 128 + h * 32 + nn];
            float v1 = src[(2 * dp + 1) * 128 + h * 32 + nn];
            split_pk(v0, v1, WCH[n * 36 + dp], WCL[n * 36 + dp]);
        }
        for (int i = tid; i < 64 * 16; i += 256) {
            int d = i & 63, kp = i >> 6;
            float v0 = wo_g[h * 2048 + (2 * kp) * 64 + d];
            float v1 = wo_g[h * 2048 + (2 * kp + 1) * 64 + d];
            split_pk(v0, v1, WOH[d * 20 + kp], WOL[d * 20 + kp]);
        }
        __syncthreads();

        // --- GEMM1 ---
        float c12[12][4];
#pragma unroll
        for (int j = 0; j < 12; j++)
#pragma unroll
            for (int i = 0; i < 4; i++) c12[j][i] = 0.f;
        for (int kk = 0; kk < 4; kk++) {
            uint32_t ah[4], al[4];
            ldAw(XHs + row0 * 36 + kk * 8, 36, g, t, ah);
            ldAw(XLs + row0 * 36 + kk * 8, 36, g, t, al);
#pragma unroll
            for (int j = 0; j < 12; j++) {
                uint32_t bh2[2], bl2[2];
                ldBw(WCH + j * 8 * 36 + kk * 8, 36, g, t, bh2);
                ldBw(WCL + j * 8 * 36 + kk * 8, 36, g, t, bl2);
                mma3(c12[j], ah, al, bh2, bl2);
            }
        }
        uint32_t QAh[2][4], QAl[2][4];
#pragma unroll
        for (int j = 0; j < 4; j++) {
            int cc = j * 8 + 2 * t;
            float b0 = bq_g[h * 32 + cc], b1 = bq_g[h * 32 + cc + 1];
            float v0 = (c12[j][0] + b0) * QSCALE, v1 = (c12[j][1] + b1) * QSCALE;
            float v2 = (c12[j][2] + b0) * QSCALE, v3 = (c12[j][3] + b1) * QSCALE;
            int kc = j >> 1, e = j & 1;
            split_pk(v0, v1, QAh[kc][2 * e],     QAl[kc][2 * e]);
            split_pk(v2, v3, QAh[kc][2 * e + 1], QAl[kc][2 * e + 1]);
        }
#pragma unroll
        for (int j = 4; j < 8; j++) {
            int cc = (j - 4) * 8 + 2 * t;
            float b0 = bk_g[h * 32 + cc], b1 = bk_g[h * 32 + cc + 1];
            int kp = cc >> 1;
            split_pk(c12[j][0] + b0, c12[j][1] + b1, KTHs[rrA * 20 + kp], KTLs[rrA * 20 + kp]);
            split_pk(c12[j][2] + b0, c12[j][3] + b1, KTHs[rrB * 20 + kp], KTLs[rrB * 20 + kp]);
        }
        {
            __nv_bfloat16* VH16 = reinterpret_cast<__nv_bfloat16*>(VTHs);
            __nv_bfloat16* VL16 = reinterpret_cast<__nv_bfloat16*>(VTLs);
#pragma unroll
            for (int j = 8; j < 12; j++) {
                int vk = (j - 8) * 8 + 2 * t;
                float b0 = bv_g[h * 32 + vk], b1 = bv_g[h * 32 + vk + 1];
                float vv[4] = {c12[j][0] + b0, c12[j][1] + b1, c12[j][2] + b0, c12[j][3] + b1};
                int   cl[4] = {vk, vk + 1, vk, vk + 1};
                int   rw[4] = {rrA, rrA, rrB, rrB};
#pragma unroll
                for (int q2 = 0; q2 < 4; q2++) {
                    __nv_bfloat16 hb = __float2bfloat16(vv[q2]);
                    float lf = vv[q2] - __bfloat162float(hb);
                    VH16[cl[q2] * 72 + rw[q2]] = hb;
                    VL16[cl[q2] * 72 + rw[q2]] = __float2bfloat16(lf);
                }
            }
        }
        __syncthreads();

        // --- S = Q K^T over 64 cols, full-row softmax ---
        float cS[8][4];
#pragma unroll
        for (int j = 0; j < 8; j++)
#pragma unroll
            for (int i = 0; i < 4; i++) cS[j][i] = 0.f;
#pragma unroll
        for (int kk = 0; kk < 2; kk++) {
#pragma unroll
            for (int j = 0; j < 8; j++) {
                uint32_t bh2[2], bl2[2];
                ldBw(KTHs + j * 8 * 20 + kk * 8, 20, g, t, bh2);
                ldBw(KTLs + j * 8 * 20 + kk * 8, 20, g, t, bl2);
                mma3(cS[j], QAh[kk], QAl[kk], bh2, bl2);
            }
        }
        float mA = cS[0][0], mB = cS[0][2];
#pragma unroll
        for (int j = 0; j < 8; j++) {
            mA = fmaxf(mA, fmaxf(cS[j][0], cS[j][1]));
            mB = fmaxf(mB, fmaxf(cS[j][2], cS[j][3]));
        }
        mA = fmaxf(mA, __shfl_xor_sync(0xffffffff, mA, 1));
        mA = fmaxf(mA, __shfl_xor_sync(0xffffffff, mA, 2));
        mB = fmaxf(mB, __shfl_xor_sync(0xffffffff, mB, 1));
        mB = fmaxf(mB, __shfl_xor_sync(0xffffffff, mB, 2));
        float sA = 0.f, sB = 0.f;
#pragma unroll
        for (int j = 0; j < 8; j++) {
            cS[j][0] = ex2f(cS[j][0] - mA); sA += cS[j][0];
            cS[j][1] = ex2f(cS[j][1] - mA); sA += cS[j][1];
            cS[j][2] = ex2f(cS[j][2] - mB); sB += cS[j][2];
            cS[j][3] = ex2f(cS[j][3] - mB); sB += cS[j][3];
        }
        sA += __shfl_xor_sync(0xffffffff, sA, 1);
        sA += __shfl_xor_sync(0xffffffff, sA, 2);
        sB += __shfl_xor_sync(0xffffffff, sB, 1);
        sB += __shfl_xor_sync(0xffffffff, sB, 2);
        float invA = __fdividef(1.f, sA), invB = __fdividef(1.f, sB);

        // P -> registers (A-frags for PV, k = s = 64 -> 4 ksteps)
        uint32_t PAh[4][4], PAl[4][4];
#pragma unroll
        for (int kc = 0; kc < 4; kc++) {
            int j0 = 2 * kc;
            split_pk(cS[j0][0] * invA,     cS[j0][1] * invA,     PAh[kc][0], PAl[kc][0]);
            split_pk(cS[j0][2] * invB,     cS[j0][3] * invB,     PAh[kc][1], PAl[kc][1]);
            split_pk(cS[j0 + 1][0] * invA, cS[j0 + 1][1] * invA, PAh[kc][2], PAl[kc][2]);
            split_pk(cS[j0 + 1][2] * invB, cS[j0 + 1][3] * invB, PAh[kc][3], PAl[kc][3]);
        }

        // --- PV ---
        float cP[4][4];
#pragma unroll
        for (int j = 0; j < 4; j++)
#pragma unroll
            for (int i = 0; i < 4; i++) cP[j][i] = 0.f;
#pragma unroll
        for (int kk = 0; kk < 4; kk++) {
#pragma unroll
            for (int j = 0; j < 4; j++) {
                uint32_t bh2[2], bl2[2];
                ldBw(VTHs + j * 8 * 36 + kk * 8, 36, g, t, bh2);
                ldBw(VTLs + j * 8 * 36 + kk * 8, 36, g, t, bl2);
                mma3(cP[j], PAh[kk], PAl[kk], bh2, bl2);
            }
        }

        // O -> registers, outproj accumulate
        uint32_t OAh[2][4], OAl[2][4];
#pragma unroll
        for (int j = 0; j < 4; j++) {
            int kc = j >> 1, e = j & 1;
            split_pk(cP[j][0], cP[j][1], OAh[kc][2 * e],     OAl[kc][2 * e]);
            split_pk(cP[j][2], cP[j][3], OAh[kc][2 * e + 1], OAl[kc][2 * e + 1]);
        }
#pragma unroll
        for (int kk = 0; kk < 2; kk++) {
#pragma unroll
            for (int j = 0; j < 8; j++) {
                uint32_t bh2[2], bl2[2];
                ldBw(WOH + j * 8 * 20 + kk * 8, 20, g, t, bh2);
                ldBw(WOL + j * 8 * 20 + kk * 8, 20, g, t, bl2);
                mma3(oacc[j], OAh[kk], OAl[kk], bh2, bl2);
            }
        }
    }

    // Write (initialize) out. rows = t, cols = d
#pragma unroll
    for (int j = 0; j < 8; j++) {
        int d0 = j * 8 + 2 * t;
        float bo0 = bo_g[d0], bo1 = bo_g[d0 + 1];
        size_t base0 = ((size_t)(b * TT + rrA) * FF + f) * DD;
        size_t base1 = ((size_t)(b * TT + rrB) * FF + f) * DD;
        out[base0 + d0]     = oacc[j][0] + bo0;
        out[base0 + d0 + 1] = oacc[j][1] + bo1;
        out[base1 + d0]     = oacc[j][2] + bo0;
        out[base1 + d0 + 1] = oacc[j][3] + bo1;
    }
}

extern "C" void kernel_launch(void* const* d_in, const int* in_sizes, int n_in,
                              void* d_out, int out_size)
{
    const float* x = (const float*)d_in[0];
    const float *tqw, *tqb, *tkw, *tkb, *tvw, *tvb, *tow, *tob;
    const float *fqw, *fqb, *fkw, *fkb, *fvw, *fvb, *fow, *fob;

    if (in_sizes[8] == 64) {  // reference-signature order
        tqw = (const float*)d_in[1];  tqb = (const float*)d_in[2];
        tkw = (const float*)d_in[3];  tkb = (const float*)d_in[4];
        tvw = (const float*)d_in[5];  tvb = (const float*)d_in[6];
        tow = (const float*)d_in[7];  tob = (const float*)d_in[8];
        fqw = (const float*)d_in[9];  fqb = (const float*)d_in[10];
        fkw = (const float*)d_in[11]; fkb = (const float*)d_in[12];
        fvw = (const float*)d_in[13]; fvb = (const float*)d_in[14];
        fow = (const float*)d_in[15]; fob = (const float*)d_in[16];
    } else {                  // setup_inputs dict order
        tqw = (const float*)d_in[1];  tqb = (const float*)d_in[2];
        tkw = (const float*)d_in[3];  tkb = (const float*)d_in[4];
        tvw = (const float*)d_in[5];  tvb = (const float*)d_in[6];
        fqw = (const float*)d_in[7];  fqb = (const float*)d_in[8];
        fkw = (const float*)d_in[9];  fkb = (const float*)d_in[10];
        fvw = (const float*)d_in[11]; fvb = (const float*)d_in[12];
        tow = (const float*)d_in[13]; tob = (const float*)d_in[14];
        fow = (const float*)d_in[15]; fob = (const float*)d_in[16];
    }

    const int SMEM_T = 28416 * 4;   // 113664 B -> 2 CTA/SM
    const int SMEM_F = 28160 * 4;   // 112640 B -> 2 CTA/SM
    cudaFuncSetAttribute(temporal_kernel,
                         cudaFuncAttributeMaxDynamicSharedMemorySize, SMEM_T);
    cudaFuncSetAttribute(feature_kernel,
                         cudaFuncAttributeMaxDynamicSharedMemorySize, SMEM_F);

    temporal_kernel<<<BB * FF / 2, 256, SMEM_T>>>(
        x, tqw, tqb, tkw, tkb, tvw, tvb, tow, tob, (float*)d_out);
    feature_kernel<<<BB * TT, 256, SMEM_F>>>(
        x, fqw, fqb, fkw, fkb, fvw, fvb, fow, fob, (float*)d_out);
}